// round 14
// baseline (speedup 1.0000x reference)
#include <cuda_runtime.h>
#include <cuda_fp16.h>
#include <cstdint>

#define Bc 64
#define Nc 512
#define Dc 256
#define Ec 128
#define NITER 20
#define NROWS (Bc*Nc)
#define NCHUNK 8
#define HS 72      // smem row stride in halves (144B, conflict-free ldmatrix, 16B-aligned)

__device__ __half g_ph[2*NROWS*Ec];        // split-hi of a(zb=0)/b(zb=1), [row][e]
__device__ __half g_pl[2*NROWS*Ec];        // split-lo
__device__ __half g_wth[2*Ec*Dc];          // W^T split-hi [zb][e][d]
__device__ __half g_wtl[2*Ec*Dc];
__device__ __half g_E[(size_t)Bc*Nc*Nc];   // fp16 K (exp; scaled in place at iter 0), 33.5MB
__device__ float  g_r1[NROWS];
__device__ float  g_r2[NROWS];
__device__ float  g_u[NROWS];
__device__ float  g_vpart[2][NCHUNK*NROWS];
__device__ float  g_rspart[4*NROWS];       // rowsum(e) partials per j-block
__device__ float  g_cspart[4*NROWS];       // colsum(e) partials per i-block
__device__ int    g_mask_mode;

// ---- helpers ----
__device__ __forceinline__ uint32_t smem_u32(const void* p) {
    uint32_t a;
    asm("{ .reg .u64 t; cvta.to.shared.u64 t, %1; cvt.u32.u64 %0, t; }" : "=r"(a) : "l"(p));
    return a;
}
__device__ __forceinline__ void ldm_x4(uint32_t* r, uint32_t addr) {
    asm volatile("ldmatrix.sync.aligned.m8n8.x4.shared.b16 {%0,%1,%2,%3}, [%4];"
        : "=r"(r[0]), "=r"(r[1]), "=r"(r[2]), "=r"(r[3]) : "r"(addr));
}
__device__ __forceinline__ void mma16816(float* c, const uint32_t* a, const uint32_t* b) {
    asm volatile("mma.sync.aligned.m16n8k16.row.col.f32.f16.f16.f32 "
        "{%0,%1,%2,%3}, {%4,%5,%6,%7}, {%8,%9}, {%0,%1,%2,%3};"
        : "+f"(c[0]), "+f"(c[1]), "+f"(c[2]), "+f"(c[3])
        : "r"(a[0]), "r"(a[1]), "r"(a[2]), "r"(a[3]), "r"(b[0]), "r"(b[1]));
}
__device__ __forceinline__ void cp16(uint32_t saddr, const void* g) {
    asm volatile("cp.async.cg.shared.global [%0], [%1], 16;" :: "r"(saddr), "l"(g));
}
#define CP_COMMIT() asm volatile("cp.async.commit_group;" ::: "memory")
#define CP_WAIT0()  asm volatile("cp.async.wait_group 0;" ::: "memory")
__device__ __forceinline__ void split16(float v, __half& h, __half& l) {
    h = __float2half_rn(v); l = __float2half_rn(v - __half2float(h));
}

// ---- mask dtype detection ----
__global__ void detect_mask_kernel(const unsigned int* __restrict__ m) {
    __shared__ int bad_i32, bad_f32;
    if (threadIdx.x == 0) { bad_i32 = 0; bad_f32 = 0; }
    __syncthreads();
    for (int i = threadIdx.x; i < 8192; i += blockDim.x) {
        unsigned int w = m[i];
        if (w != 0u && w != 1u)          atomicOr(&bad_i32, 1);
        if (w != 0u && w != 0x3F800000u) atomicOr(&bad_f32, 1);
    }
    __syncthreads();
    if (threadIdx.x == 0) g_mask_mode = bad_i32 ? (bad_f32 ? 2 : 1) : 0;
}
__device__ __forceinline__ bool read_mask(const void* mp, int row) {
    int mode = g_mask_mode;
    if (mode == 2) return ((const unsigned char*)mp)[row] != 0;
    if (mode == 1) return ((const float*)mp)[row] != 0.0f;
    return ((const int*)mp)[row] != 0;
}

// ---- W transpose + split ----
__global__ __launch_bounds__(256) void wsplit_kernel(const float* __restrict__ Wa,
                                                     const float* __restrict__ Wb) {
    int idx = blockIdx.x * 256 + threadIdx.x;       // < 2*128*256
    int zb = idx >> 15, loc = idx & 32767;
    int e = loc >> 8, d = loc & 255;
    const float* W = zb ? Wb : Wa;
    __half h, l; split16(W[d * Ec + e], h, l);
    g_wth[idx] = h; g_wtl[idx] = l;
}

// ---- prep MMA: split(X @ W [*w_aff]); CTA 128 rows x 128(E); K=256 in 4 BK=64 chunks ----
#define SMEM_GEMM (4 * 128 * HS * 2)   // 73728 B
__global__ __launch_bounds__(256) void prep_mma_kernel(
    const float* __restrict__ in_emb, const void* __restrict__ maskp,
    const float* __restrict__ out_emb, const float* __restrict__ pad,
    const float* __restrict__ pos, const float* __restrict__ w_aff) {
    extern __shared__ __half sh[];
    __half* Xh = sh;            __half* Xl = sh + 128 * HS;
    __half* Wh = sh + 2*128*HS; __half* Wl = sh + 3*128*HS;
    const int tid = threadIdx.x, wid = tid >> 5, lane = tid & 31;
    const int row0 = blockIdx.x * 128, zb = blockIdx.y;
    const int wm = wid >> 2, wn = wid & 3;
    float c[4][4][4] = {};
    const uint32_t aXh = smem_u32(Xh), aXl = smem_u32(Xl);
    const uint32_t aWh = smem_u32(Wh), aWl = smem_u32(Wl);

    for (int chk = 0; chk < 4; chk++) {
        // W tiles: async gmem->smem copies, issued first so they run under X work
        {
            const uint4* gwh = (const uint4*)g_wth;
            const uint4* gwl = (const uint4*)g_wtl;
            #pragma unroll
            for (int it = 0; it < 4; it++) {       // 128 e-rows x 8 uint4
                int idx = it * 256 + tid;
                int e = idx >> 3, u4 = idx & 7;
                size_t gi = (size_t)(zb * 128 + e) * 32 + chk * 8 + u4;
                uint32_t boff = (uint32_t)((e * HS + u4 * 8) * 2);
                cp16(aWh + boff, &gwh[gi]);
                cp16(aWl + boff, &gwl[gi]);
            }
            CP_COMMIT();
        }
        // X: fp32 load + split + smem store (overlaps the async W copies)
        #pragma unroll
        for (int it = 0; it < 8; it++) {           // 128 rows x 16 float4 (64 d)
            int idx = it * 256 + tid;
            int r = idx >> 4, f4 = idx & 15;
            int grow = row0 + r, d = chk * 64 + f4 * 4;
            float4 v;
            if (zb == 0) {
                float4 a4 = *(const float4*)&out_emb[(size_t)grow * Dc + d];
                float4 p4 = *(const float4*)&pos[(grow & (Nc - 1)) * Dc + d];
                v = make_float4(a4.x + p4.x, a4.y + p4.y, a4.z + p4.z, a4.w + p4.w);
            } else {
                if (read_mask(maskp, grow)) v = *(const float4*)&pad[d];
                else                        v = *(const float4*)&in_emb[(size_t)grow * Dc + d];
            }
            __half hx, lx, hy, ly, hz, lz, hw, lw;
            split16(v.x, hx, lx); split16(v.y, hy, ly);
            split16(v.z, hz, lz); split16(v.w, hw, lw);
            __half2 h01 = __halves2half2(hx, hy), h23 = __halves2half2(hz, hw);
            __half2 l01 = __halves2half2(lx, ly), l23 = __halves2half2(lz, lw);
            uint2 qh, ql;
            qh.x = *(uint32_t*)&h01; qh.y = *(uint32_t*)&h23;
            ql.x = *(uint32_t*)&l01; ql.y = *(uint32_t*)&l23;
            int off = r * HS + f4 * 4;
            *(uint2*)(Xh + off) = qh;  *(uint2*)(Xl + off) = ql;
        }
        CP_WAIT0();
        __syncthreads();
        #pragma unroll
        for (int k16 = 0; k16 < 4; k16++) {
            int kb = k16 * 16;
            uint32_t ah[4][4], al[4][4], bh[4][2], bl[4][2];
            #pragma unroll
            for (int mt = 0; mt < 4; mt++) {
                int r = wm * 64 + mt * 16 + (lane & 15);
                uint32_t byt = (uint32_t)((r * HS + kb + (lane >> 4) * 8) * 2);
                ldm_x4(ah[mt], aXh + byt);
                ldm_x4(al[mt], aXl + byt);
            }
            #pragma unroll
            for (int np = 0; np < 2; np++) {
                int mat = lane >> 3;
                int n = wn * 32 + np * 16 + (mat >> 1) * 8 + (lane & 7);
                uint32_t byt = (uint32_t)((n * HS + kb + (mat & 1) * 8) * 2);
                uint32_t t[4];
                ldm_x4(t, aWh + byt);
                bh[np*2][0] = t[0]; bh[np*2][1] = t[1];
                bh[np*2+1][0] = t[2]; bh[np*2+1][1] = t[3];
                ldm_x4(t, aWl + byt);
                bl[np*2][0] = t[0]; bl[np*2][1] = t[1];
                bl[np*2+1][0] = t[2]; bl[np*2+1][1] = t[3];
            }
            #pragma unroll
            for (int mt = 0; mt < 4; mt++)
                #pragma unroll
                for (int nt = 0; nt < 4; nt++) {
                    mma16816(c[mt][nt], ah[mt], bh[nt]);
                    mma16816(c[mt][nt], ah[mt], bl[nt]);
                    mma16816(c[mt][nt], al[mt], bh[nt]);
                }
        }
        __syncthreads();
    }
    const size_t zoff = (size_t)zb * NROWS * Ec;
    #pragma unroll
    for (int mt = 0; mt < 4; mt++)
        #pragma unroll
        for (int nt = 0; nt < 4; nt++) {
            int e = wn * 32 + nt * 8 + (lane & 3) * 2;
            float w0 = 1.f, w1 = 1.f;
            if (zb == 0) { float2 wv = __ldg((const float2*)&w_aff[e]); w0 = wv.x; w1 = wv.y; }
            #pragma unroll
            for (int h = 0; h < 2; h++) {
                int row = row0 + wm * 64 + mt * 16 + (lane >> 2) + h * 8;
                float f0 = c[mt][nt][h*2] * w0, f1 = c[mt][nt][h*2+1] * w1;
                __half h0, l0, h1, l1;
                split16(f0, h0, l0); split16(f1, h1, l1);
                *(__half2*)(g_ph + zoff + (size_t)row * Ec + e) = __halves2half2(h0, h1);
                *(__half2*)(g_pl + zoff + (size_t)row * Ec + e) = __halves2half2(l0, l1);
            }
        }
}

// ---- aff MMA: g_E = fp16(exp(aff+b-5)) + fused row/col sum partials ----
__global__ __launch_bounds__(256) void aff_mma_kernel(const float* __restrict__ baff) {
    extern __shared__ __half sh[];
    __shared__ float s_row[16][128];
    __shared__ float s_col[16][128];
    __half* Ah = sh;            __half* Al = sh + 128 * HS;
    __half* Bh = sh + 2*128*HS; __half* Bl = sh + 3*128*HS;
    const int tid = threadIdx.x, wid = tid >> 5, lane = tid & 31;
    const int i0 = blockIdx.x * 128, j0 = blockIdx.y * 128, b = blockIdx.z;
    const int wm = wid >> 2, wn = wid & 3;
    float c[4][4][4] = {};
    const uint32_t aAh = smem_u32(Ah), aAl = smem_u32(Al);
    const uint32_t aBh = smem_u32(Bh), aBl = smem_u32(Bl);

    const uint4* gah = (const uint4*)(g_ph + ((size_t)b * Nc + i0) * Ec);
    const uint4* gal = (const uint4*)(g_pl + ((size_t)b * Nc + i0) * Ec);
    const uint4* gbh = (const uint4*)(g_ph + (size_t)NROWS * Ec + ((size_t)b * Nc + j0) * Ec);
    const uint4* gbl = (const uint4*)(g_pl + (size_t)NROWS * Ec + ((size_t)b * Nc + j0) * Ec);

    for (int chk = 0; chk < 2; chk++) {
        #pragma unroll
        for (int it = 0; it < 4; it++) {           // A & B: 128 rows x 8 uint4 each
            int idx = it * 256 + tid;
            int r = idx >> 3, u4 = idx & 7;
            uint32_t boff = (uint32_t)((r * HS + u4 * 8) * 2);
            size_t gi = (size_t)r * 16 + chk * 8 + u4;
            cp16(aAh + boff, &gah[gi]);
            cp16(aAl + boff, &gal[gi]);
            cp16(aBh + boff, &gbh[gi]);
            cp16(aBl + boff, &gbl[gi]);
        }
        CP_COMMIT();
        CP_WAIT0();
        __syncthreads();
        #pragma unroll
        for (int k16 = 0; k16 < 4; k16++) {
            int kb = k16 * 16;
            uint32_t ah[4][4], al[4][4], bh[4][2], bl[4][2];
            #pragma unroll
            for (int mt = 0; mt < 4; mt++) {
                int r = wm * 64 + mt * 16 + (lane & 15);
                uint32_t byt = (uint32_t)((r * HS + kb + (lane >> 4) * 8) * 2);
                ldm_x4(ah[mt], aAh + byt);
                ldm_x4(al[mt], aAl + byt);
            }
            #pragma unroll
            for (int np = 0; np < 2; np++) {
                int mat = lane >> 3;
                int n = wn * 32 + np * 16 + (mat >> 1) * 8 + (lane & 7);
                uint32_t byt = (uint32_t)((n * HS + kb + (mat & 1) * 8) * 2);
                uint32_t t[4];
                ldm_x4(t, aBh + byt);
                bh[np*2][0] = t[0]; bh[np*2][1] = t[1];
                bh[np*2+1][0] = t[2]; bh[np*2+1][1] = t[3];
                ldm_x4(t, aBl + byt);
                bl[np*2][0] = t[0]; bl[np*2][1] = t[1];
                bl[np*2+1][0] = t[2]; bl[np*2+1][1] = t[3];
            }
            #pragma unroll
            for (int mt = 0; mt < 4; mt++)
                #pragma unroll
                for (int nt = 0; nt < 4; nt++) {
                    mma16816(c[mt][nt], ah[mt], bh[nt]);
                    mma16816(c[mt][nt], ah[mt], bl[nt]);
                    mma16816(c[mt][nt], al[mt], bh[nt]);
                }
        }
        __syncthreads();
    }
    const float bv = __ldg(baff) - 5.0f;
    float rsum8[8] = {}, csum8[8] = {};
    #pragma unroll
    for (int mt = 0; mt < 4; mt++)
        #pragma unroll
        for (int nt = 0; nt < 4; nt++) {
            int j = j0 + wn * 32 + nt * 8 + (lane & 3) * 2;
            #pragma unroll
            for (int h = 0; h < 2; h++) {
                int i = i0 + wm * 64 + mt * 16 + (lane >> 2) + h * 8;
                float e0 = __expf(c[mt][nt][h*2]   + bv);
                float e1 = __expf(c[mt][nt][h*2+1] + bv);
                *(__half2*)(g_E + ((size_t)b * Nc + i) * Nc + j) = __floats2half2_rn(e0, e1);
                rsum8[mt*2+h] += e0 + e1;
                csum8[nt*2]   += e0;
                csum8[nt*2+1] += e1;
            }
        }
    {
        int rsl = wn * 4 + (lane & 3);
        int csl = wm * 8 + (lane >> 2);
        #pragma unroll
        for (int mt = 0; mt < 4; mt++)
            #pragma unroll
            for (int h = 0; h < 2; h++)
                s_row[rsl][wm * 64 + mt * 16 + (lane >> 2) + h * 8] = rsum8[mt*2+h];
        #pragma unroll
        for (int nt = 0; nt < 4; nt++)
            #pragma unroll
            for (int p = 0; p < 2; p++)
                s_col[csl][wn * 32 + nt * 8 + (lane & 3) * 2 + p] = csum8[nt*2+p];
    }
    __syncthreads();
    if (tid < 128) {
        float s = 0.f;
        #pragma unroll
        for (int k = 0; k < 16; k++) s += s_row[k][tid];
        g_rspart[(size_t)blockIdx.y * NROWS + b * Nc + i0 + tid] = s;
    } else {
        int t = tid - 128;
        float s = 0.f;
        #pragma unroll
        for (int k = 0; k < 16; k++) s += s_col[k][t];
        g_cspart[(size_t)blockIdx.x * NROWS + b * Nc + j0 + t] = s;
    }
}

// ---- r1/r2 finalize (4 partials each) ----
__global__ __launch_bounds__(256) void rfin_kernel() {
    int idx = blockIdx.x * 256 + threadIdx.x;
    float rs = 0.f, cs = 0.f;
    #pragma unroll
    for (int p = 0; p < 4; p++) {
        rs += g_rspart[(size_t)p * NROWS + idx];
        cs += g_cspart[(size_t)p * NROWS + idx];
    }
    g_r2[idx] = 0.5f / rs;
    g_r1[idx] = 0.5f / cs;
}

__global__ __launch_bounds__(256) void vinit_kernel() {
    int idx = blockIdx.x * 256 + threadIdx.x;
    g_vpart[0][idx] = (idx < NROWS) ? 1.0f : 0.0f;
}

// ---- fused Sinkhorn iteration; iter 0 also folds (r1_j + r2_i) into g_E in place ----
__global__ __launch_bounds__(512) void sink_iter_kernel(int pr, int sc) {
    __shared__ float v_s[512];
    __shared__ float rs[16][8];
    __shared__ float u_s[64];
    __shared__ float pbuf[8][512];
    __shared__ float r1_s[512];
    __shared__ float r2_s[64];
    const int c = blockIdx.x, b = blockIdx.y, tid = threadIdx.x;
    const int ig = tid >> 6, jg = tid & 63;
    const int lane = tid & 31, warp = tid >> 5;

    {
        float s = 0.f;
        #pragma unroll
        for (int cc = 0; cc < NCHUNK; cc++)
            s += g_vpart[pr][(size_t)cc * NROWS + b * Nc + tid];
        v_s[tid] = 1.0f / s;
        if (sc) {
            r1_s[tid] = g_r1[b * Nc + tid];
            if (tid < 64) r2_s[tid] = g_r2[b * Nc + c * 64 + tid];
        }
    }
    // load this thread's 8x8 K sub-block (coalesced LDG.128, MLP=8)
    uint4* gk = (uint4*)(g_E + ((size_t)b * Nc + c * 64) * Nc);
    uint4 q[8];
    #pragma unroll
    for (int ii = 0; ii < 8; ii++) q[ii] = gk[(ig * 8 + ii) * 64 + jg];
    __syncthreads();

    if (sc) {   // fold (r1_j + r2_i) into the tile, write back (block owns tile exclusively)
        float r1v[8];
        *(float4*)&r1v[0] = *(float4*)&r1_s[jg * 8];
        *(float4*)&r1v[4] = *(float4*)&r1_s[jg * 8 + 4];
        #pragma unroll
        for (int ii = 0; ii < 8; ii++) {
            float r2v = r2_s[ig * 8 + ii];
            float2 f0 = __half22float2(*(__half2*)&q[ii].x);
            float2 f1 = __half22float2(*(__half2*)&q[ii].y);
            float2 f2 = __half22float2(*(__half2*)&q[ii].z);
            float2 f3 = __half22float2(*(__half2*)&q[ii].w);
            __half2 o0 = __floats2half2_rn(f0.x * (r1v[0] + r2v), f0.y * (r1v[1] + r2v));
            __half2 o1 = __floats2half2_rn(f1.x * (r1v[2] + r2v), f1.y * (r1v[3] + r2v));
            __half2 o2 = __floats2half2_rn(f2.x * (r1v[4] + r2v), f2.y * (r1v[5] + r2v));
            __half2 o3 = __floats2half2_rn(f3.x * (r1v[6] + r2v), f3.y * (r1v[7] + r2v));
            q[ii].x = *(uint32_t*)&o0; q[ii].y = *(uint32_t*)&o1;
            q[ii].z = *(uint32_t*)&o2; q[ii].w = *(uint32_t*)&o3;
            gk[(ig * 8 + ii) * 64 + jg] = q[ii];
        }
    }

    // row pass
    float vr[8];
    *(float4*)&vr[0] = *(float4*)&v_s[jg * 8];
    *(float4*)&vr[4] = *(float4*)&v_s[jg * 8 + 4];
    float rp[8];
    #pragma unroll
    for (int ii = 0; ii < 8; ii++) {
        float2 f0 = __half22float2(*(__half2*)&q[ii].x);
        float2 f1 = __half22float2(*(__half2*)&q[ii].y);
        float2 f2 = __half22float2(*(__half2*)&q[ii].z);
        float2 f3 = __half22float2(*(__half2*)&q[ii].w);
        rp[ii] = f0.x*vr[0] + f0.y*vr[1] + f1.x*vr[2] + f1.y*vr[3]
               + f2.x*vr[4] + f2.y*vr[5] + f3.x*vr[6] + f3.y*vr[7];
    }
    #pragma unroll
    for (int o = 16; o; o >>= 1)
        #pragma unroll
        for (int ii = 0; ii < 8; ii++)
            rp[ii] += __shfl_xor_sync(0xffffffffu, rp[ii], o);
    if (lane == 0) {
        #pragma unroll
        for (int ii = 0; ii < 8; ii++) rs[warp][ii] = rp[ii];
    }
    __syncthreads();
    if (tid < 64) {
        int g2 = tid >> 3, ii = tid & 7;
        float u = 1.0f / (rs[2*g2][ii] + rs[2*g2+1][ii]);
        u_s[tid] = u;
        g_u[b * Nc + c * 64 + tid] = u;
    }
    __syncthreads();

    // col pass (reuse registers)
    float cp[8] = {};
    #pragma unroll
    for (int ii = 0; ii < 8; ii++) {
        float ui = u_s[ig * 8 + ii];
        float2 f0 = __half22float2(*(__half2*)&q[ii].x);
        float2 f1 = __half22float2(*(__half2*)&q[ii].y);
        float2 f2 = __half22float2(*(__half2*)&q[ii].z);
        float2 f3 = __half22float2(*(__half2*)&q[ii].w);
        cp[0] += f0.x * ui; cp[1] += f0.y * ui;
        cp[2] += f1.x * ui; cp[3] += f1.y * ui;
        cp[4] += f2.x * ui; cp[5] += f2.y * ui;
        cp[6] += f3.x * ui; cp[7] += f3.y * ui;
    }
    *(float4*)&pbuf[ig][jg * 8]     = *(float4*)&cp[0];
    *(float4*)&pbuf[ig][jg * 8 + 4] = *(float4*)&cp[4];
    __syncthreads();
    {
        float s = 0.f;
        #pragma unroll
        for (int ii = 0; ii < 8; ii++) s += pbuf[ii][tid];
        g_vpart[pr ^ 1][(size_t)c * NROWS + b * Nc + tid] = s;
    }
}

// ---- final: out = Kscaled * u_i * v_j ----
__global__ __launch_bounds__(512) void final_kernel(float* __restrict__ out, int pr) {
    __shared__ float u_s[64];
    __shared__ float v_sh[512];
    const int c = blockIdx.x, b = blockIdx.y, tid = threadIdx.x;
    {
        float s = 0.f;
        #pragma unroll
        for (int cc = 0; cc < NCHUNK; cc++)
            s += g_vpart[pr][(size_t)cc * NROWS + b * Nc + tid];
        v_sh[tid] = 1.0f / s;
    }
    if (tid < 64) u_s[tid] = g_u[b * Nc + c * 64 + tid];
    __syncthreads();
    const uint4* kp = (const uint4*)(g_E + ((size_t)b * Nc + c * 64) * Nc);
    #pragma unroll
    for (int it = 0; it < 8; it++) {
        int idx = tid + it * 512;
        int i = idx >> 6, j4 = idx & 63;
        uint4 q = kp[idx];
        float ui = u_s[i];
        const float* vp = &v_sh[j4 * 8];
        float2 f0 = __half22float2(*(__half2*)&q.x);
        float2 f1 = __half22float2(*(__half2*)&q.y);
        float2 f2 = __half22float2(*(__half2*)&q.z);
        float2 f3 = __half22float2(*(__half2*)&q.w);
        float4 o0 = make_float4(f0.x*ui*vp[0], f0.y*ui*vp[1], f1.x*ui*vp[2], f1.y*ui*vp[3]);
        float4 o1 = make_float4(f2.x*ui*vp[4], f2.y*ui*vp[5], f3.x*ui*vp[6], f3.y*ui*vp[7]);
        size_t off = ((size_t)b * Nc + c * 64 + i) * Nc + j4 * 8;
        *(float4*)&out[off]     = o0;
        *(float4*)&out[off + 4] = o1;
    }
}

// ---- launch ----
extern "C" void kernel_launch(void* const* d_in, const int* in_sizes, int n_in,
                              void* d_out, int out_size) {
    const float* in_emb  = (const float*)d_in[0];
    const void*  maskp   = d_in[1];
    const float* out_emb = (const float*)d_in[2];
    const float* pad     = (const float*)d_in[3];
    const float* pos     = (const float*)d_in[4];
    const float* Wa      = (const float*)d_in[5];
    const float* Wb      = (const float*)d_in[6];
    const float* w_aff   = (const float*)d_in[7];
    const float* baff    = (const float*)d_in[8];

    cudaFuncSetAttribute(prep_mma_kernel, cudaFuncAttributeMaxDynamicSharedMemorySize, SMEM_GEMM);
    cudaFuncSetAttribute(aff_mma_kernel,  cudaFuncAttributeMaxDynamicSharedMemorySize, SMEM_GEMM);

    detect_mask_kernel<<<1, 256>>>((const unsigned int*)maskp);
    wsplit_kernel<<<256, 256>>>(Wa, Wb);
    vinit_kernel<<<(NCHUNK * NROWS) / 256, 256>>>();
    prep_mma_kernel<<<dim3(NROWS / 128, 2), 256, SMEM_GEMM>>>(in_emb, maskp, out_emb, pad, pos, w_aff);
    aff_mma_kernel<<<dim3(4, 4, Bc), 256, SMEM_GEMM>>>(baff);
    rfin_kernel<<<NROWS / 256, 256>>>();
    for (int t = 0; t < NITER; t++)
        sink_iter_kernel<<<dim3(NCHUNK, Bc), 512>>>(t & 1, t == 0);
    final_kernel<<<dim3(NCHUNK, Bc), 512>>>((float*)d_out, NITER & 1);
}

// round 15
// speedup vs baseline: 1.1529x; 1.1529x over previous
#include <cuda_runtime.h>
#include <cuda_fp16.h>
#include <cstdint>

#define Bc 64
#define Nc 512
#define Dc 256
#define Ec 128
#define NITER 20
#define NROWS (Bc*Nc)
#define NCHUNK 8
#define HS 72      // smem row stride in halves (144B, conflict-free ldmatrix, 16B-aligned)

__device__ __half g_ph[2*NROWS*Ec];        // split-hi of a(zb=0)/b(zb=1), [row][e]
__device__ __half g_pl[2*NROWS*Ec];        // split-lo
__device__ __half g_wth[2*Ec*Dc];          // W^T split-hi [zb][e][d]
__device__ __half g_wtl[2*Ec*Dc];
__device__ __half g_E[(size_t)Bc*Nc*Nc];   // fp16 K (exp; scaled in place at iter 0), 33.5MB
__device__ float  g_r1[NROWS];
__device__ float  g_r2[NROWS];
__device__ float  g_u[NROWS];
__device__ float  g_vpart[2][NCHUNK*NROWS];
__device__ float  g_rspart[4*NROWS];       // rowsum(e) partials per j-block
__device__ float  g_cspart[4*NROWS];       // colsum(e) partials per i-block
__device__ int    g_mask_mode;

// ---- helpers ----
__device__ __forceinline__ uint32_t smem_u32(const void* p) {
    uint32_t a;
    asm("{ .reg .u64 t; cvta.to.shared.u64 t, %1; cvt.u32.u64 %0, t; }" : "=r"(a) : "l"(p));
    return a;
}
__device__ __forceinline__ void ldm_x4(uint32_t* r, uint32_t addr) {
    asm volatile("ldmatrix.sync.aligned.m8n8.x4.shared.b16 {%0,%1,%2,%3}, [%4];"
        : "=r"(r[0]), "=r"(r[1]), "=r"(r[2]), "=r"(r[3]) : "r"(addr));
}
__device__ __forceinline__ void mma16816(float* c, const uint32_t* a, const uint32_t* b) {
    asm volatile("mma.sync.aligned.m16n8k16.row.col.f32.f16.f16.f32 "
        "{%0,%1,%2,%3}, {%4,%5,%6,%7}, {%8,%9}, {%0,%1,%2,%3};"
        : "+f"(c[0]), "+f"(c[1]), "+f"(c[2]), "+f"(c[3])
        : "r"(a[0]), "r"(a[1]), "r"(a[2]), "r"(a[3]), "r"(b[0]), "r"(b[1]));
}
__device__ __forceinline__ void split16(float v, __half& h, __half& l) {
    h = __float2half_rn(v); l = __float2half_rn(v - __half2float(h));
}

// ---- mask dtype detection ----
__global__ void detect_mask_kernel(const unsigned int* __restrict__ m) {
    __shared__ int bad_i32, bad_f32;
    if (threadIdx.x == 0) { bad_i32 = 0; bad_f32 = 0; }
    __syncthreads();
    for (int i = threadIdx.x; i < 8192; i += blockDim.x) {
        unsigned int w = m[i];
        if (w != 0u && w != 1u)          atomicOr(&bad_i32, 1);
        if (w != 0u && w != 0x3F800000u) atomicOr(&bad_f32, 1);
    }
    __syncthreads();
    if (threadIdx.x == 0) g_mask_mode = bad_i32 ? (bad_f32 ? 2 : 1) : 0;
}
__device__ __forceinline__ bool read_mask(const void* mp, int row) {
    int mode = g_mask_mode;
    if (mode == 2) return ((const unsigned char*)mp)[row] != 0;
    if (mode == 1) return ((const float*)mp)[row] != 0.0f;
    return ((const int*)mp)[row] != 0;
}

// ---- W transpose + split ----
__global__ __launch_bounds__(256) void wsplit_kernel(const float* __restrict__ Wa,
                                                     const float* __restrict__ Wb) {
    int idx = blockIdx.x * 256 + threadIdx.x;       // < 2*128*256
    int zb = idx >> 15, loc = idx & 32767;
    int e = loc >> 8, d = loc & 255;
    const float* W = zb ? Wb : Wa;
    __half h, l; split16(W[d * Ec + e], h, l);
    g_wth[idx] = h; g_wtl[idx] = l;
}

// ---- prep MMA (round-12 form): split(X @ W [*w_aff]); CTA 128x128(E); K=256, BK=64 ----
#define SMEM_GEMM (4 * 128 * HS * 2)   // 73728 B
__global__ __launch_bounds__(256) void prep_mma_kernel(
    const float* __restrict__ in_emb, const void* __restrict__ maskp,
    const float* __restrict__ out_emb, const float* __restrict__ pad,
    const float* __restrict__ pos, const float* __restrict__ w_aff) {
    extern __shared__ __half sh[];
    __half* Xh = sh;            __half* Xl = sh + 128 * HS;
    __half* Wh = sh + 2*128*HS; __half* Wl = sh + 3*128*HS;
    const int tid = threadIdx.x, wid = tid >> 5, lane = tid & 31;
    const int row0 = blockIdx.x * 128, zb = blockIdx.y;
    const int wm = wid >> 2, wn = wid & 3;
    float c[4][4][4] = {};

    for (int chk = 0; chk < 4; chk++) {
        #pragma unroll
        for (int it = 0; it < 8; it++) {           // X: 128 rows x 16 float4 (64 d)
            int idx = it * 256 + tid;
            int r = idx >> 4, f4 = idx & 15;
            int grow = row0 + r, d = chk * 64 + f4 * 4;
            float4 v;
            if (zb == 0) {
                float4 a4 = *(const float4*)&out_emb[(size_t)grow * Dc + d];
                float4 p4 = *(const float4*)&pos[(grow & (Nc - 1)) * Dc + d];
                v = make_float4(a4.x + p4.x, a4.y + p4.y, a4.z + p4.z, a4.w + p4.w);
            } else {
                if (read_mask(maskp, grow)) v = *(const float4*)&pad[d];
                else                        v = *(const float4*)&in_emb[(size_t)grow * Dc + d];
            }
            __half hx, lx, hy, ly, hz, lz, hw, lw;
            split16(v.x, hx, lx); split16(v.y, hy, ly);
            split16(v.z, hz, lz); split16(v.w, hw, lw);
            __half2 h01 = __halves2half2(hx, hy), h23 = __halves2half2(hz, hw);
            __half2 l01 = __halves2half2(lx, ly), l23 = __halves2half2(lz, lw);
            uint2 qh, ql;
            qh.x = *(uint32_t*)&h01; qh.y = *(uint32_t*)&h23;
            ql.x = *(uint32_t*)&l01; ql.y = *(uint32_t*)&l23;
            int off = r * HS + f4 * 4;
            *(uint2*)(Xh + off) = qh;  *(uint2*)(Xl + off) = ql;
        }
        {
            const uint4* gwh = (const uint4*)g_wth;
            const uint4* gwl = (const uint4*)g_wtl;
            #pragma unroll
            for (int it = 0; it < 4; it++) {       // W: 128 e-rows x 8 uint4
                int idx = it * 256 + tid;
                int e = idx >> 3, u4 = idx & 7;
                size_t gi = (size_t)(zb * 128 + e) * 32 + chk * 8 + u4;
                int off = e * HS + u4 * 8;
                *(uint4*)(Wh + off) = gwh[gi];  *(uint4*)(Wl + off) = gwl[gi];
            }
        }
        __syncthreads();
        const uint32_t aXh = smem_u32(Xh), aXl = smem_u32(Xl);
        const uint32_t aWh = smem_u32(Wh), aWl = smem_u32(Wl);
        #pragma unroll
        for (int k16 = 0; k16 < 4; k16++) {
            int kb = k16 * 16;
            uint32_t ah[4][4], al[4][4], bh[4][2], bl[4][2];
            #pragma unroll
            for (int mt = 0; mt < 4; mt++) {
                int r = wm * 64 + mt * 16 + (lane & 15);
                uint32_t byt = (uint32_t)((r * HS + kb + (lane >> 4) * 8) * 2);
                ldm_x4(ah[mt], aXh + byt);
                ldm_x4(al[mt], aXl + byt);
            }
            #pragma unroll
            for (int np = 0; np < 2; np++) {
                int mat = lane >> 3;
                int n = wn * 32 + np * 16 + (mat >> 1) * 8 + (lane & 7);
                uint32_t byt = (uint32_t)((n * HS + kb + (mat & 1) * 8) * 2);
                uint32_t t[4];
                ldm_x4(t, aWh + byt);
                bh[np*2][0] = t[0]; bh[np*2][1] = t[1];
                bh[np*2+1][0] = t[2]; bh[np*2+1][1] = t[3];
                ldm_x4(t, aWl + byt);
                bl[np*2][0] = t[0]; bl[np*2][1] = t[1];
                bl[np*2+1][0] = t[2]; bl[np*2+1][1] = t[3];
            }
            #pragma unroll
            for (int mt = 0; mt < 4; mt++)
                #pragma unroll
                for (int nt = 0; nt < 4; nt++) {
                    mma16816(c[mt][nt], ah[mt], bh[nt]);
                    mma16816(c[mt][nt], ah[mt], bl[nt]);
                    mma16816(c[mt][nt], al[mt], bh[nt]);
                }
        }
        __syncthreads();
    }
    const size_t zoff = (size_t)zb * NROWS * Ec;
    #pragma unroll
    for (int mt = 0; mt < 4; mt++)
        #pragma unroll
        for (int nt = 0; nt < 4; nt++) {
            int e = wn * 32 + nt * 8 + (lane & 3) * 2;
            float w0 = 1.f, w1 = 1.f;
            if (zb == 0) { float2 wv = __ldg((const float2*)&w_aff[e]); w0 = wv.x; w1 = wv.y; }
            #pragma unroll
            for (int h = 0; h < 2; h++) {
                int row = row0 + wm * 64 + mt * 16 + (lane >> 2) + h * 8;
                float f0 = c[mt][nt][h*2] * w0, f1 = c[mt][nt][h*2+1] * w1;
                __half h0, l0, h1, l1;
                split16(f0, h0, l0); split16(f1, h1, l1);
                *(__half2*)(g_ph + zoff + (size_t)row * Ec + e) = __halves2half2(h0, h1);
                *(__half2*)(g_pl + zoff + (size_t)row * Ec + e) = __halves2half2(l0, l1);
            }
        }
}

// ---- aff MMA: round-12 tile loads + fused exp row/col sum partial epilogue ----
__global__ __launch_bounds__(256) void aff_mma_kernel(const float* __restrict__ baff) {
    extern __shared__ __half sh[];
    __shared__ float s_row[16][128];
    __shared__ float s_col[16][128];
    __half* Ah = sh;            __half* Al = sh + 128 * HS;
    __half* Bh = sh + 2*128*HS; __half* Bl = sh + 3*128*HS;
    const int tid = threadIdx.x, wid = tid >> 5, lane = tid & 31;
    const int i0 = blockIdx.x * 128, j0 = blockIdx.y * 128, b = blockIdx.z;
    const int wm = wid >> 2, wn = wid & 3;
    float c[4][4][4] = {};

    const uint4* gah = (const uint4*)(g_ph + ((size_t)b * Nc + i0) * Ec);
    const uint4* gal = (const uint4*)(g_pl + ((size_t)b * Nc + i0) * Ec);
    const uint4* gbh = (const uint4*)(g_ph + (size_t)NROWS * Ec + ((size_t)b * Nc + j0) * Ec);
    const uint4* gbl = (const uint4*)(g_pl + (size_t)NROWS * Ec + ((size_t)b * Nc + j0) * Ec);

    for (int chk = 0; chk < 2; chk++) {
        #pragma unroll
        for (int it = 0; it < 4; it++) {           // A: 128 rows x 8 uint4
            int idx = it * 256 + tid;
            int r = idx >> 3, u4 = idx & 7;
            int off = r * HS + u4 * 8;
            size_t gi = (size_t)r * 16 + chk * 8 + u4;
            *(uint4*)(Ah + off) = gah[gi];  *(uint4*)(Al + off) = gal[gi];
        }
        #pragma unroll
        for (int it = 0; it < 4; it++) {           // B: 128 rows x 8 uint4
            int idx = it * 256 + tid;
            int r = idx >> 3, u4 = idx & 7;
            int off = r * HS + u4 * 8;
            size_t gi = (size_t)r * 16 + chk * 8 + u4;
            *(uint4*)(Bh + off) = gbh[gi];  *(uint4*)(Bl + off) = gbl[gi];
        }
        __syncthreads();
        const uint32_t aAh = smem_u32(Ah), aAl = smem_u32(Al);
        const uint32_t aBh = smem_u32(Bh), aBl = smem_u32(Bl);
        #pragma unroll
        for (int k16 = 0; k16 < 4; k16++) {
            int kb = k16 * 16;
            uint32_t ah[4][4], al[4][4], bh[4][2], bl[4][2];
            #pragma unroll
            for (int mt = 0; mt < 4; mt++) {
                int r = wm * 64 + mt * 16 + (lane & 15);
                uint32_t byt = (uint32_t)((r * HS + kb + (lane >> 4) * 8) * 2);
                ldm_x4(ah[mt], aAh + byt);
                ldm_x4(al[mt], aAl + byt);
            }
            #pragma unroll
            for (int np = 0; np < 2; np++) {
                int mat = lane >> 3;
                int n = wn * 32 + np * 16 + (mat >> 1) * 8 + (lane & 7);
                uint32_t byt = (uint32_t)((n * HS + kb + (mat & 1) * 8) * 2);
                uint32_t t[4];
                ldm_x4(t, aBh + byt);
                bh[np*2][0] = t[0]; bh[np*2][1] = t[1];
                bh[np*2+1][0] = t[2]; bh[np*2+1][1] = t[3];
                ldm_x4(t, aBl + byt);
                bl[np*2][0] = t[0]; bl[np*2][1] = t[1];
                bl[np*2+1][0] = t[2]; bl[np*2+1][1] = t[3];
            }
            #pragma unroll
            for (int mt = 0; mt < 4; mt++)
                #pragma unroll
                for (int nt = 0; nt < 4; nt++) {
                    mma16816(c[mt][nt], ah[mt], bh[nt]);
                    mma16816(c[mt][nt], ah[mt], bl[nt]);
                    mma16816(c[mt][nt], al[mt], bh[nt]);
                }
        }
        __syncthreads();
    }
    const float bv = __ldg(baff) - 5.0f;
    float rsum8[8] = {}, csum8[8] = {};
    #pragma unroll
    for (int mt = 0; mt < 4; mt++)
        #pragma unroll
        for (int nt = 0; nt < 4; nt++) {
            int j = j0 + wn * 32 + nt * 8 + (lane & 3) * 2;
            #pragma unroll
            for (int h = 0; h < 2; h++) {
                int i = i0 + wm * 64 + mt * 16 + (lane >> 2) + h * 8;
                float e0 = __expf(c[mt][nt][h*2]   + bv);
                float e1 = __expf(c[mt][nt][h*2+1] + bv);
                *(__half2*)(g_E + ((size_t)b * Nc + i) * Nc + j) = __floats2half2_rn(e0, e1);
                rsum8[mt*2+h] += e0 + e1;
                csum8[nt*2]   += e0;
                csum8[nt*2+1] += e1;
            }
        }
    {
        int rsl = wn * 4 + (lane & 3);
        int csl = wm * 8 + (lane >> 2);
        #pragma unroll
        for (int mt = 0; mt < 4; mt++)
            #pragma unroll
            for (int h = 0; h < 2; h++)
                s_row[rsl][wm * 64 + mt * 16 + (lane >> 2) + h * 8] = rsum8[mt*2+h];
        #pragma unroll
        for (int nt = 0; nt < 4; nt++)
            #pragma unroll
            for (int p = 0; p < 2; p++)
                s_col[csl][wn * 32 + nt * 8 + (lane & 3) * 2 + p] = csum8[nt*2+p];
    }
    __syncthreads();
    if (tid < 128) {
        float s = 0.f;
        #pragma unroll
        for (int k = 0; k < 16; k++) s += s_row[k][tid];
        g_rspart[(size_t)blockIdx.y * NROWS + b * Nc + i0 + tid] = s;
    } else {
        int t = tid - 128;
        float s = 0.f;
        #pragma unroll
        for (int k = 0; k < 16; k++) s += s_col[k][t];
        g_cspart[(size_t)blockIdx.x * NROWS + b * Nc + j0 + t] = s;
    }
}

// ---- r1/r2 finalize (4 partials each) ----
__global__ __launch_bounds__(256) void rfin_kernel() {
    int idx = blockIdx.x * 256 + threadIdx.x;
    float rs = 0.f, cs = 0.f;
    #pragma unroll
    for (int p = 0; p < 4; p++) {
        rs += g_rspart[(size_t)p * NROWS + idx];
        cs += g_cspart[(size_t)p * NROWS + idx];
    }
    g_r2[idx] = 0.5f / rs;
    g_r1[idx] = 0.5f / cs;
}

__global__ __launch_bounds__(256) void vinit_kernel() {
    int idx = blockIdx.x * 256 + threadIdx.x;
    g_vpart[0][idx] = (idx < NROWS) ? 1.0f : 0.0f;
}

// ---- fused Sinkhorn iteration; iter 0 also folds (r1_j + r2_i) into g_E in place ----
__global__ __launch_bounds__(512) void sink_iter_kernel(int pr, int sc) {
    __shared__ float v_s[512];
    __shared__ float rs[16][8];
    __shared__ float u_s[64];
    __shared__ float pbuf[8][512];
    __shared__ float r1_s[512];
    __shared__ float r2_s[64];
    const int c = blockIdx.x, b = blockIdx.y, tid = threadIdx.x;
    const int ig = tid >> 6, jg = tid & 63;
    const int lane = tid & 31, warp = tid >> 5;

    {
        float s = 0.f;
        #pragma unroll
        for (int cc = 0; cc < NCHUNK; cc++)
            s += g_vpart[pr][(size_t)cc * NROWS + b * Nc + tid];
        v_s[tid] = 1.0f / s;
        if (sc) {
            r1_s[tid] = g_r1[b * Nc + tid];
            if (tid < 64) r2_s[tid] = g_r2[b * Nc + c * 64 + tid];
        }
    }
    uint4* gk = (uint4*)(g_E + ((size_t)b * Nc + c * 64) * Nc);
    uint4 q[8];
    #pragma unroll
    for (int ii = 0; ii < 8; ii++) q[ii] = gk[(ig * 8 + ii) * 64 + jg];
    __syncthreads();

    if (sc) {   // fold (r1_j + r2_i) into the tile, write back (block owns tile exclusively)
        float r1v[8];
        *(float4*)&r1v[0] = *(float4*)&r1_s[jg * 8];
        *(float4*)&r1v[4] = *(float4*)&r1_s[jg * 8 + 4];
        #pragma unroll
        for (int ii = 0; ii < 8; ii++) {
            float r2v = r2_s[ig * 8 + ii];
            float2 f0 = __half22float2(*(__half2*)&q[ii].x);
            float2 f1 = __half22float2(*(__half2*)&q[ii].y);
            float2 f2 = __half22float2(*(__half2*)&q[ii].z);
            float2 f3 = __half22float2(*(__half2*)&q[ii].w);
            __half2 o0 = __floats2half2_rn(f0.x * (r1v[0] + r2v), f0.y * (r1v[1] + r2v));
            __half2 o1 = __floats2half2_rn(f1.x * (r1v[2] + r2v), f1.y * (r1v[3] + r2v));
            __half2 o2 = __floats2half2_rn(f2.x * (r1v[4] + r2v), f2.y * (r1v[5] + r2v));
            __half2 o3 = __floats2half2_rn(f3.x * (r1v[6] + r2v), f3.y * (r1v[7] + r2v));
            q[ii].x = *(uint32_t*)&o0; q[ii].y = *(uint32_t*)&o1;
            q[ii].z = *(uint32_t*)&o2; q[ii].w = *(uint32_t*)&o3;
            gk[(ig * 8 + ii) * 64 + jg] = q[ii];
        }
    }

    // row pass
    float vr[8];
    *(float4*)&vr[0] = *(float4*)&v_s[jg * 8];
    *(float4*)&vr[4] = *(float4*)&v_s[jg * 8 + 4];
    float rp[8];
    #pragma unroll
    for (int ii = 0; ii < 8; ii++) {
        float2 f0 = __half22float2(*(__half2*)&q[ii].x);
        float2 f1 = __half22float2(*(__half2*)&q[ii].y);
        float2 f2 = __half22float2(*(__half2*)&q[ii].z);
        float2 f3 = __half22float2(*(__half2*)&q[ii].w);
        rp[ii] = f0.x*vr[0] + f0.y*vr[1] + f1.x*vr[2] + f1.y*vr[3]
               + f2.x*vr[4] + f2.y*vr[5] + f3.x*vr[6] + f3.y*vr[7];
    }
    #pragma unroll
    for (int o = 16; o; o >>= 1)
        #pragma unroll
        for (int ii = 0; ii < 8; ii++)
            rp[ii] += __shfl_xor_sync(0xffffffffu, rp[ii], o);
    if (lane == 0) {
        #pragma unroll
        for (int ii = 0; ii < 8; ii++) rs[warp][ii] = rp[ii];
    }
    __syncthreads();
    if (tid < 64) {
        int g2 = tid >> 3, ii = tid & 7;
        float u = 1.0f / (rs[2*g2][ii] + rs[2*g2+1][ii]);
        u_s[tid] = u;
        g_u[b * Nc + c * 64 + tid] = u;
    }
    __syncthreads();

    // col pass (reuse registers)
    float cp[8] = {};
    #pragma unroll
    for (int ii = 0; ii < 8; ii++) {
        float ui = u_s[ig * 8 + ii];
        float2 f0 = __half22float2(*(__half2*)&q[ii].x);
        float2 f1 = __half22float2(*(__half2*)&q[ii].y);
        float2 f2 = __half22float2(*(__half2*)&q[ii].z);
        float2 f3 = __half22float2(*(__half2*)&q[ii].w);
        cp[0] += f0.x * ui; cp[1] += f0.y * ui;
        cp[2] += f1.x * ui; cp[3] += f1.y * ui;
        cp[4] += f2.x * ui; cp[5] += f2.y * ui;
        cp[6] += f3.x * ui; cp[7] += f3.y * ui;
    }
    *(float4*)&pbuf[ig][jg * 8]     = *(float4*)&cp[0];
    *(float4*)&pbuf[ig][jg * 8 + 4] = *(float4*)&cp[4];
    __syncthreads();
    {
        float s = 0.f;
        #pragma unroll
        for (int ii = 0; ii < 8; ii++) s += pbuf[ii][tid];
        g_vpart[pr ^ 1][(size_t)c * NROWS + b * Nc + tid] = s;
    }
}

// ---- final: out = Kscaled * u_i * v_j ----
__global__ __launch_bounds__(512) void final_kernel(float* __restrict__ out, int pr) {
    __shared__ float u_s[64];
    __shared__ float v_sh[512];
    const int c = blockIdx.x, b = blockIdx.y, tid = threadIdx.x;
    {
        float s = 0.f;
        #pragma unroll
        for (int cc = 0; cc < NCHUNK; cc++)
            s += g_vpart[pr][(size_t)cc * NROWS + b * Nc + tid];
        v_sh[tid] = 1.0f / s;
    }
    if (tid < 64) u_s[tid] = g_u[b * Nc + c * 64 + tid];
    __syncthreads();
    const uint4* kp = (const uint4*)(g_E + ((size_t)b * Nc + c * 64) * Nc);
    #pragma unroll
    for (int it = 0; it < 8; it++) {
        int idx = tid + it * 512;
        int i = idx >> 6, j4 = idx & 63;
        uint4 q = kp[idx];
        float ui = u_s[i];
        const float* vp = &v_sh[j4 * 8];
        float2 f0 = __half22float2(*(__half2*)&q.x);
        float2 f1 = __half22float2(*(__half2*)&q.y);
        float2 f2 = __half22float2(*(__half2*)&q.z);
        float2 f3 = __half22float2(*(__half2*)&q.w);
        float4 o0 = make_float4(f0.x*ui*vp[0], f0.y*ui*vp[1], f1.x*ui*vp[2], f1.y*ui*vp[3]);
        float4 o1 = make_float4(f2.x*ui*vp[4], f2.y*ui*vp[5], f3.x*ui*vp[6], f3.y*ui*vp[7]);
        size_t off = ((size_t)b * Nc + c * 64 + i) * Nc + j4 * 8;
        *(float4*)&out[off]     = o0;
        *(float4*)&out[off + 4] = o1;
    }
}

// ---- launch ----
extern "C" void kernel_launch(void* const* d_in, const int* in_sizes, int n_in,
                              void* d_out, int out_size) {
    const float* in_emb  = (const float*)d_in[0];
    const void*  maskp   = d_in[1];
    const float* out_emb = (const float*)d_in[2];
    const float* pad     = (const float*)d_in[3];
    const float* pos     = (const float*)d_in[4];
    const float* Wa      = (const float*)d_in[5];
    const float* Wb      = (const float*)d_in[6];
    const float* w_aff   = (const float*)d_in[7];
    const float* baff    = (const float*)d_in[8];

    cudaFuncSetAttribute(prep_mma_kernel, cudaFuncAttributeMaxDynamicSharedMemorySize, SMEM_GEMM);
    cudaFuncSetAttribute(aff_mma_kernel,  cudaFuncAttributeMaxDynamicSharedMemorySize, SMEM_GEMM);

    detect_mask_kernel<<<1, 256>>>((const unsigned int*)maskp);
    wsplit_kernel<<<256, 256>>>(Wa, Wb);
    vinit_kernel<<<(NCHUNK * NROWS) / 256, 256>>>();
    prep_mma_kernel<<<dim3(NROWS / 128, 2), 256, SMEM_GEMM>>>(in_emb, maskp, out_emb, pad, pos, w_aff);
    aff_mma_kernel<<<dim3(4, 4, Bc), 256, SMEM_GEMM>>>(baff);
    rfin_kernel<<<NROWS / 256, 256>>>();
    for (int t = 0; t < NITER; t++)
        sink_iter_kernel<<<dim3(NCHUNK, Bc), 512>>>(t & 1, t == 0);
    final_kernel<<<dim3(NCHUNK, Bc), 512>>>((float*)d_out, NITER & 1);
}